// round 15
// baseline (speedup 1.0000x reference)
#include <cuda_runtime.h>
#include <cuda_fp16.h>
#include <cstdint>
#include <math.h>

#define DD 1024
#define TT 4096
#define BB 4
#define EPSF 1e-6f

#define BM 128
#define BN 64            // per weight matrix; one head per block in out_kernel
#define BK 64            // halves per K-chunk (=128 bytes/row)
#define NCHUNK (DD/BK)   // 16
#define NTHREADS 256
#define NSTAGE 3

#define A_TILE_B  (BM*BK*2)                 // 16384
#define B_TILE_B  (BN*BK*2)                 // 8192
#define STAGE_B   (A_TILE_B + 2*B_TILE_B)   // 32768
#define OFF_STATS (NSTAGE*STAGE_B)          // 98304
#define SMEM_TOTAL (OFF_STATS + 2048)       // 100352

#define NRB (BB*TT/BM)   // 128 row blocks

// Deterministic two-stage reduction buffers
__device__ float g_pk  [NRB*DD];
__device__ float g_pkv [NRB*DD];
__device__ float g_ksum [BB*DD];
__device__ float g_kvsum[BB*DD];
// fp16 copies (converted once per launch)
__device__ __align__(16) __half g_Xh [BB*TT*DD];
__device__ __align__(16) __half g_Wqh[DD*DD];
__device__ __align__(16) __half g_Wkh[DD*DD];
__device__ __align__(16) __half g_Wvh[DD*DD];
__device__ __align__(16) __half g_Wgh[DD*DD];

// ---------------------------------------------------------------- helpers ---
__device__ __forceinline__ uint32_t smem_u32(const void* p) {
    uint32_t a;
    asm("{ .reg .u64 t; cvta.to.shared.u64 t, %1; cvt.u32.u64 %0, t; }" : "=r"(a) : "l"(p));
    return a;
}
__device__ __forceinline__ void cp16(uint32_t dst, const void* src) {
    asm volatile("cp.async.cg.shared.global [%0], [%1], 16;" :: "r"(dst), "l"(src));
}
__device__ __forceinline__ void cp_commit() { asm volatile("cp.async.commit_group;" ::: "memory"); }
template <int N> __device__ __forceinline__ void cp_wait() {
    asm volatile("cp.async.wait_group %0;" :: "n"(N) : "memory");
}
__device__ __forceinline__ void mma_f16(float* d, const uint32_t* a, const uint32_t* b) {
    asm volatile("mma.sync.aligned.m16n8k16.row.col.f32.f16.f16.f32 "
                 "{%0,%1,%2,%3}, {%4,%5,%6,%7}, {%8,%9}, {%0,%1,%2,%3};"
                 : "+f"(d[0]), "+f"(d[1]), "+f"(d[2]), "+f"(d[3])
                 : "r"(a[0]), "r"(a[1]), "r"(a[2]), "r"(a[3]), "r"(b[0]), "r"(b[1]));
}
#define LDSM4(r0, r1, r2, r3, addr) \
    asm volatile("ldmatrix.sync.aligned.m8n8.x4.shared.b16 {%0,%1,%2,%3}, [%4];" \
                 : "=r"(r0), "=r"(r1), "=r"(r2), "=r"(r3) : "r"(addr))
__device__ __forceinline__ float phi_f(float x) { return x > 0.f ? x + 1.f : __expf(x); }
__device__ __forceinline__ float sigm(float x) { return 1.f / (1.f + __expf(-x)); }

// Load one K-chunk into a stage: A 128x64h, B1 64x64h, B2 64x64h (256 threads)
// Rows are 128 bytes; 16B groups XORed with (row&7) — conflict-free.
__device__ __forceinline__ void load_stage(uint32_t sbase,
                                           const __half* A, const __half* B1, const __half* B2,
                                           int tid)
{
#pragma unroll
    for (int p = 0; p < 4; p++) {           // A: 1024 x 16B
        int idx = p * NTHREADS + tid;
        int row = idx >> 3, cg = idx & 7;
        cp16(sbase + row * 128 + ((cg ^ (row & 7)) << 4),
             (const char*)A + (size_t)row * (DD*2) + cg * 16);
    }
#pragma unroll
    for (int p = 0; p < 2; p++) {           // B1: 512 x 16B
        int idx = p * NTHREADS + tid;
        int row = idx >> 3, cg = idx & 7;
        cp16(sbase + A_TILE_B + row * 128 + ((cg ^ (row & 7)) << 4),
             (const char*)B1 + (size_t)row * (DD*2) + cg * 16);
    }
#pragma unroll
    for (int p = 0; p < 2; p++) {           // B2: 512 x 16B
        int idx = p * NTHREADS + tid;
        int row = idx >> 3, cg = idx & 7;
        cp16(sbase + A_TILE_B + B_TILE_B + row * 128 + ((cg ^ (row & 7)) << 4),
             (const char*)B2 + (size_t)row * (DD*2) + cg * 16);
    }
}

// 3-stage double-output fp16 GEMM mainloop, 8 warps, ldmatrix fragment loads.
// ONE barrier per chunk (R14-proven). Matrix-sequential inner loop: per ks,
// A+B1 loads -> mat1 MMAs -> B2 loads -> mat2 MMAs. B2's LDSMs overlap mat1's
// MMAs; next ks's A/B1 LDSMs overlap mat2's MMAs. Peak live fragment regs 16.
// Warp tile: 32M (wm = wid&3) x 32N (wn = wid>>2) per matrix.
__device__ __forceinline__ void run_gemm2(uint32_t sb,
                                          const __half* A, const __half* B1, const __half* B2,
                                          int tid, float acc1[2][4][4], float acc2[2][4][4])
{
    const int wid = tid >> 5, lane = tid & 31;
    const int wm = wid & 3, wn = wid >> 2;
    const int l7 = lane & 7;

    const int rowA = wm * 32 + (lane & 15);
    const int hA   = lane >> 4;
    const int rowB = wn * 32 + l7 + ((lane >> 4) << 3);
    const int hB   = (lane >> 3) & 1;

#pragma unroll
    for (int m = 0; m < 2; m++)
#pragma unroll
        for (int nt = 0; nt < 4; nt++)
#pragma unroll
            for (int r = 0; r < 4; r++) { acc1[m][nt][r] = 0.f; acc2[m][nt][r] = 0.f; }

    // Prologue: stage 0,1 in flight; certify stage 0 for all warps.
    load_stage(sb + 0*STAGE_B, A,      B1,      B2,      tid); cp_commit();
    load_stage(sb + 1*STAGE_B, A + BK, B1 + BK, B2 + BK, tid); cp_commit();
    cp_wait<1>();
    __syncthreads();

    for (int c = 0; c < NCHUNK; c++) {
        const int s = c % NSTAGE;
        const uint32_t sA  = sb + s * STAGE_B;
        const uint32_t sB1 = sA + A_TILE_B;
        const uint32_t sB2 = sB1 + B_TILE_B;
        const uint32_t baseA0 = sA  + (uint32_t)rowA * 128;          // m=0
        const uint32_t baseA1 = baseA0 + 16 * 128;                   // m=1
        const uint32_t bB10 = sB1 + (uint32_t)rowB * 128;            // pair 0
        const uint32_t bB11 = bB10 + 16 * 128;                       // pair 1
        const uint32_t bB20 = sB2 + (uint32_t)rowB * 128;
        const uint32_t bB21 = bB20 + 16 * 128;

#pragma unroll
        for (int ks = 0; ks < 4; ks++) {
            // Mid-chunk: issue next-next chunk's loads between ks=1 and ks=2.
            if (ks == 2 && c + 2 < NCHUNK) {
                const int k0 = (c + 2) * BK;
                load_stage(sb + ((c + 2) % NSTAGE) * STAGE_B, A + k0, B1 + k0, B2 + k0, tid);
                cp_commit();
            }
            const uint32_t gA = (uint32_t)((((ks << 1) | hA) ^ l7) << 4);
            const uint32_t gB = (uint32_t)((((ks << 1) | hB) ^ l7) << 4);

            uint32_t af0[4], af1[4];
            LDSM4(af0[0], af0[1], af0[2], af0[3], baseA0 + gA);
            LDSM4(af1[0], af1[1], af1[2], af1[3], baseA1 + gA);

            uint32_t bf1r[4][2];
            LDSM4(bf1r[0][0], bf1r[0][1], bf1r[1][0], bf1r[1][1], bB10 + gB);
            LDSM4(bf1r[2][0], bf1r[2][1], bf1r[3][0], bf1r[3][1], bB11 + gB);
#pragma unroll
            for (int nt = 0; nt < 4; nt++) {
                mma_f16(acc1[0][nt], af0, bf1r[nt]);
                mma_f16(acc1[1][nt], af1, bf1r[nt]);
            }

            uint32_t bf2r[4][2];
            LDSM4(bf2r[0][0], bf2r[0][1], bf2r[1][0], bf2r[1][1], bB20 + gB);
            LDSM4(bf2r[2][0], bf2r[2][1], bf2r[3][0], bf2r[3][1], bB21 + gB);
#pragma unroll
            for (int nt = 0; nt < 4; nt++) {
                mma_f16(acc2[0][nt], af0, bf2r[nt]);
                mma_f16(acc2[1][nt], af1, bf2r[nt]);
            }
        }

        // Certify chunk c+1 for the next iteration, then the single barrier.
        if (c + 2 < NCHUNK)      cp_wait<1>();   // outstanding {c+1, c+2} -> oldest done
        else if (c + 1 < NCHUNK) cp_wait<0>();   // only {c+1} outstanding -> drain
        __syncthreads();
    }
}

// ---------------------------------------------------------------------------
// Kernel 0: convert all 5 tensors fp32 -> fp16 in ONE launch (flat index)
// ---------------------------------------------------------------------------
__global__ void cvt_all_kernel(const float4* __restrict__ x,
                               const float4* __restrict__ wq, const float4* __restrict__ wk,
                               const float4* __restrict__ wv, const float4* __restrict__ wg,
                               uint2* __restrict__ xo,
                               uint2* __restrict__ qo, uint2* __restrict__ ko,
                               uint2* __restrict__ vo, uint2* __restrict__ go,
                               int nX4, int nW4)
{
    int i = blockIdx.x * blockDim.x + threadIdx.x;
    const float4* s; uint2* d; int j;
    if (i < nX4) { s = x; d = xo; j = i; }
    else {
        int r = i - nX4;
        int t = r / nW4;          // 0..3
        j = r - t * nW4;
        if (j >= nW4) return;
        switch (t) {
            case 0: s = wq; d = qo; break;
            case 1: s = wk; d = ko; break;
            case 2: s = wv; d = vo; break;
            case 3: s = wg; d = go; break;
            default: return;
        }
    }
    float4 v = s[j];
    __half2 h0 = __floats2half2_rn(v.x, v.y);
    __half2 h1 = __floats2half2_rn(v.z, v.w);
    uint2 o;
    o.x = *(uint32_t*)&h0;
    o.y = *(uint32_t*)&h1;
    d[j] = o;
}

// ---------------------------------------------------------------------------
// Kernel 1: K=phi(X@Wk^T), V=X@Wv^T; per-rowblock column sums of phi(K), phi(K)*V.
// In-register epilogue: shuffle-reduce over rows, tiny smem fold across warps.
// grid = (DD/BN=16, NRB=128), 256 threads
// ---------------------------------------------------------------------------
__global__ void __launch_bounds__(NTHREADS, 2)
stats_kernel(const __half* __restrict__ X, const __half* __restrict__ Wk,
             const __half* __restrict__ Wv)
{
    extern __shared__ char smem[];
    uint32_t sb = smem_u32(smem);
    const int tid = threadIdx.x;
    const int row0 = blockIdx.y * BM, col0 = blockIdx.x * BN;

    float accK[2][4][4], accV[2][4][4];
    run_gemm2(sb, X + (size_t)row0 * DD, Wk + (size_t)col0 * DD,
              Wv + (size_t)col0 * DD, tid, accK, accV);

    const int wid = tid >> 5, lane = tid & 31;
    const int wm = wid & 3, wn = wid >> 2;
    const int lm4 = lane & 3;

    // Thread-local: sum over this thread's 4 rows for each of its 8 columns.
    float pk[4][2], pkv[4][2];
#pragma unroll
    for (int nt = 0; nt < 4; nt++)
#pragma unroll
        for (int cc = 0; cc < 2; cc++) {
            float sk = 0.f, skv = 0.f;
#pragma unroll
            for (int m = 0; m < 2; m++)
#pragma unroll
                for (int half = 0; half < 2; half++) {
                    float kv = phi_f(accK[m][nt][half * 2 + cc]);
                    sk  += kv;
                    skv += kv * accV[m][nt][half * 2 + cc];
                }
            pk[nt][cc] = sk;
            pkv[nt][cc] = skv;
        }

    // Reduce over the l4 axis (lanes lane&3 == const, 8 rows apart): 3 shuffles.
#pragma unroll
    for (int nt = 0; nt < 4; nt++)
#pragma unroll
        for (int cc = 0; cc < 2; cc++) {
#pragma unroll
            for (int off = 16; off >= 4; off >>= 1) {
                pk[nt][cc]  += __shfl_down_sync(0xffffffffu, pk[nt][cc],  off);
                pkv[nt][cc] += __shfl_down_sync(0xffffffffu, pkv[nt][cc], off);
            }
        }

    // Lanes 0-3 hold the 32-row sums for their columns; fold across wm warps.
    float* partA = (float*)(smem + OFF_STATS);        // [4 wm][64]
    float* partB = partA + 256;                       // [4 wm][64]
    if (lane < 4) {
#pragma unroll
        for (int nt = 0; nt < 4; nt++) {
            const int col = wn * 32 + nt * 8 + lm4 * 2;
            partA[wm * 64 + col]     = pk[nt][0];
            partA[wm * 64 + col + 1] = pk[nt][1];
            partB[wm * 64 + col]     = pkv[nt][0];
            partB[wm * 64 + col + 1] = pkv[nt][1];
        }
    }
    __syncthreads();
    if (tid < 64) {
        float sa = partA[tid] + partA[64 + tid] + partA[128 + tid] + partA[192 + tid];
        float sv = partB[tid] + partB[64 + tid] + partB[128 + tid] + partB[192 + tid];
        size_t o = (size_t)blockIdx.y * DD + col0 + tid;
        g_pk[o]  = sa;
        g_pkv[o] = sv;
    }
}

// ---------------------------------------------------------------------------
// Kernel 2: fold 32 row-block partials per batch (vectorized float4 over d)
// ---------------------------------------------------------------------------
__global__ void reduce_stats_kernel() {
    int i4 = blockIdx.x * blockDim.x + threadIdx.x;   // over BB*DD/4 = 4096
    if (i4 >= BB * DD / 4) return;
    int b = i4 >> 8;                // DD/4 = 256 float4 per batch
    int d4 = i4 & 255;
    float4 sk = make_float4(0.f, 0.f, 0.f, 0.f);
    float4 skv = make_float4(0.f, 0.f, 0.f, 0.f);
    int rb0 = b * (NRB / BB);
    for (int rb = 0; rb < NRB / BB; rb++) {
        const float4 pk  = *(const float4*)&g_pk [(size_t)(rb0 + rb) * DD + d4 * 4];
        const float4 pkv = *(const float4*)&g_pkv[(size_t)(rb0 + rb) * DD + d4 * 4];
        sk.x += pk.x;  sk.y += pk.y;  sk.z += pk.z;  sk.w += pk.w;
        skv.x += pkv.x; skv.y += pkv.y; skv.z += pkv.z; skv.w += pkv.w;
    }
    *(float4*)&g_ksum [b * DD + d4 * 4] = sk;
    *(float4*)&g_kvsum[b * DD + d4 * 4] = skv;
}

// ---------------------------------------------------------------------------
// Kernel 3: Q=phi(X@Wq^T), G=X@Wg^T; s,z per row; gated output.
// grid = (16, 128); block column == one head (BN = HD = 64). 256 threads.
// ---------------------------------------------------------------------------
__global__ void __launch_bounds__(NTHREADS, 2)
out_kernel(const __half* __restrict__ Xh, const __half* __restrict__ Wq,
           const __half* __restrict__ Wg, const float* __restrict__ bgv,
           const float* __restrict__ X, float* __restrict__ out)
{
    extern __shared__ char smem[];
    uint32_t sb = smem_u32(smem);
    const int tid = threadIdx.x;
    const int row0 = blockIdx.y * BM, col0 = blockIdx.x * BN;
    const int b = row0 / TT;

    // Dedicated (non-aliased) stats region
    float* kvsS  = (float*)(smem + OFF_STATS);   // [64]
    float* ksS   = kvsS + 64;                    // [64]
    float* bgS   = ksS + 64;                     // [64]
    float* ratio = bgS + 64;                     // [128]
    if (tid < 64) {
        kvsS[tid] = g_kvsum[b * DD + col0 + tid];
        ksS[tid]  = g_ksum [b * DD + col0 + tid];
        bgS[tid]  = bgv[col0 + tid];
    }
    __syncthreads();

    float accQ[2][4][4], accG[2][4][4];
    run_gemm2(sb, Xh + (size_t)row0 * DD, Wq + (size_t)col0 * DD,
              Wg + (size_t)col0 * DD, tid, accQ, accG);

    const int wid = tid >> 5, lane = tid & 31;
    const int wm = wid & 3, wn = wid >> 2;
    const int l4 = lane >> 2, lm4 = lane & 3;

    // Partial s,z per (row, thread-slice): 8 partials per row
    float* red_s = (float*)smem;          // [128][8]
    float* red_z = red_s + 128 * 8;       // [128][8]
    const int sl = wn * 4 + lm4;
#pragma unroll
    for (int m = 0; m < 2; m++)
#pragma unroll
        for (int half = 0; half < 2; half++) {
            const int row = wm * 32 + m * 16 + l4 + half * 8;
            float s = 0.f, z = 0.f;
#pragma unroll
            for (int nt = 0; nt < 4; nt++) {
                const int col = wn * 32 + nt * 8 + lm4 * 2;
#pragma unroll
                for (int cc = 0; cc < 2; cc++) {
                    float q = phi_f(accQ[m][nt][half * 2 + cc]);
                    s += q * kvsS[col + cc];
                    z += q * ksS[col + cc];
                }
            }
            red_s[row * 8 + sl] = s;
            red_z[row * 8 + sl] = z;
        }
    __syncthreads();
    if (tid < 128) {
        float s = 0.f, z = 0.f;
#pragma unroll
        for (int j = 0; j < 8; j++) { s += red_s[tid * 8 + j]; z += red_z[tid * 8 + j]; }
        ratio[tid] = s / (z + EPSF);
    }
    __syncthreads();

    // Gate + mix, direct float2 stores (uses ORIGINAL fp32 X for the mix)
#pragma unroll
    for (int m = 0; m < 2; m++)
#pragma unroll
        for (int half = 0; half < 2; half++) {
            const int row = wm * 32 + m * 16 + l4 + half * 8;
            const float rt = ratio[row];
            const size_t rbase = (size_t)(row0 + row) * DD + col0;
#pragma unroll
            for (int nt = 0; nt < 4; nt++) {
                const int col = wn * 32 + nt * 8 + lm4 * 2;
                const float2 x2 = *(const float2*)&X[rbase + col];
                float g0 = sigm(accG[m][nt][half * 2 + 0] + bgS[col + 0]);
                float g1 = sigm(accG[m][nt][half * 2 + 1] + bgS[col + 1]);
                float2 o;
                o.x = g0 * rt + (1.f - g0) * x2.x;
                o.y = g1 * rt + (1.f - g1) * x2.y;
                *(float2*)&out[rbase + col] = o;
            }
        }
}

// ---------------------------------------------------------------------------
extern "C" void kernel_launch(void* const* d_in, const int* in_sizes, int n_in,
                              void* d_out, int out_size)
{
    const float* x  = (const float*)d_in[0];
    const float* Wq = (const float*)d_in[1];
    const float* Wk = (const float*)d_in[2];
    const float* Wv = (const float*)d_in[3];
    // d_in[4] = Wo — unused by the reference computation
    const float* Wg = (const float*)d_in[5];
    const float* bg = (const float*)d_in[6];
    float* out = (float*)d_out;

    cudaFuncSetAttribute(stats_kernel, cudaFuncAttributeMaxDynamicSharedMemorySize, SMEM_TOTAL);
    cudaFuncSetAttribute(out_kernel,   cudaFuncAttributeMaxDynamicSharedMemorySize, SMEM_TOTAL);

    __half *Xh, *Wqh, *Wkh, *Wvh, *Wgh;
    cudaGetSymbolAddress((void**)&Xh,  g_Xh);
    cudaGetSymbolAddress((void**)&Wqh, g_Wqh);
    cudaGetSymbolAddress((void**)&Wkh, g_Wkh);
    cudaGetSymbolAddress((void**)&Wvh, g_Wvh);
    cudaGetSymbolAddress((void**)&Wgh, g_Wgh);

    const int nX4 = BB*TT*DD/4, nW4 = DD*DD/4;
    const int nTot = nX4 + 4 * nW4;
    cvt_all_kernel<<<(nTot + 255)/256, 256>>>(
        (const float4*)x, (const float4*)Wq, (const float4*)Wk,
        (const float4*)Wv, (const float4*)Wg,
        (uint2*)Xh, (uint2*)Wqh, (uint2*)Wkh, (uint2*)Wvh, (uint2*)Wgh, nX4, nW4);

    dim3 grid(DD / BN, NRB);   // (16, 128)
    stats_kernel<<<grid, NTHREADS, SMEM_TOTAL>>>(Xh, Wkh, Wvh);
    reduce_stats_kernel<<<8, 256>>>();
    out_kernel<<<grid, NTHREADS, SMEM_TOTAL>>>(Xh, Wqh, Wgh, bg, x, out);
}

// round 16
// speedup vs baseline: 1.4106x; 1.4106x over previous
#include <cuda_runtime.h>
#include <cuda_fp16.h>
#include <cstdint>
#include <math.h>

#define DD 1024
#define TT 4096
#define BB 4
#define EPSF 1e-6f

#define BM 128
#define BN 64            // per weight matrix; one head per block in out_kernel
#define BK 64            // halves per K-chunk (=128 bytes/row)
#define NCHUNK (DD/BK)   // 16
#define NTHREADS 256
#define NSTAGE 3

#define A_TILE_B  (BM*BK*2)                 // 16384
#define B_TILE_B  (BN*BK*2)                 // 8192
#define STAGE_B   (A_TILE_B + 2*B_TILE_B)   // 32768
#define OFF_STATS (NSTAGE*STAGE_B)          // 98304
#define SMEM_TOTAL (OFF_STATS + 2048)       // 100352

#define NRB (BB*TT/BM)   // 128 row blocks

// Deterministic two-stage reduction buffers
__device__ float g_pk  [NRB*DD];
__device__ float g_pkv [NRB*DD];
__device__ float g_ksum [BB*DD];
__device__ float g_kvsum[BB*DD];
// fp16 copies (converted once per launch)
__device__ __align__(16) __half g_Xh [BB*TT*DD];
__device__ __align__(16) __half g_Wqh[DD*DD];
__device__ __align__(16) __half g_Wkh[DD*DD];
__device__ __align__(16) __half g_Wvh[DD*DD];
__device__ __align__(16) __half g_Wgh[DD*DD];

// ---------------------------------------------------------------- helpers ---
__device__ __forceinline__ uint32_t smem_u32(const void* p) {
    uint32_t a;
    asm("{ .reg .u64 t; cvta.to.shared.u64 t, %1; cvt.u32.u64 %0, t; }" : "=r"(a) : "l"(p));
    return a;
}
__device__ __forceinline__ void cp16(uint32_t dst, const void* src) {
    asm volatile("cp.async.cg.shared.global [%0], [%1], 16;" :: "r"(dst), "l"(src));
}
// L1-caching variant: co-resident CTAs (consecutive blockIdx.x, same row-block)
// load IDENTICAL A tiles -> second CTA hits L1.
__device__ __forceinline__ void cp16_ca(uint32_t dst, const void* src) {
    asm volatile("cp.async.ca.shared.global [%0], [%1], 16;" :: "r"(dst), "l"(src));
}
__device__ __forceinline__ void cp_commit() { asm volatile("cp.async.commit_group;" ::: "memory"); }
template <int N> __device__ __forceinline__ void cp_wait() {
    asm volatile("cp.async.wait_group %0;" :: "n"(N) : "memory");
}
__device__ __forceinline__ void mma_f16(float* d, const uint32_t* a, const uint32_t* b) {
    asm volatile("mma.sync.aligned.m16n8k16.row.col.f32.f16.f16.f32 "
                 "{%0,%1,%2,%3}, {%4,%5,%6,%7}, {%8,%9}, {%0,%1,%2,%3};"
                 : "+f"(d[0]), "+f"(d[1]), "+f"(d[2]), "+f"(d[3])
                 : "r"(a[0]), "r"(a[1]), "r"(a[2]), "r"(a[3]), "r"(b[0]), "r"(b[1]));
}
#define LDSM4(r0, r1, r2, r3, addr) \
    asm volatile("ldmatrix.sync.aligned.m8n8.x4.shared.b16 {%0,%1,%2,%3}, [%4];" \
                 : "=r"(r0), "=r"(r1), "=r"(r2), "=r"(r3) : "r"(addr))
__device__ __forceinline__ float phi_f(float x) { return x > 0.f ? x + 1.f : __expf(x); }
__device__ __forceinline__ float sigm(float x) { return 1.f / (1.f + __expf(-x)); }

// Load one K-chunk into a stage: A 128x64h, B1 64x64h, B2 64x64h (256 threads)
// Rows are 128 bytes; 16B groups XORed with (row&7) — conflict-free.
__device__ __forceinline__ void load_stage(uint32_t sbase,
                                           const __half* A, const __half* B1, const __half* B2,
                                           int tid)
{
#pragma unroll
    for (int p = 0; p < 4; p++) {           // A: 1024 x 16B (L1-cached; cross-CTA reuse)
        int idx = p * NTHREADS + tid;
        int row = idx >> 3, cg = idx & 7;
        cp16_ca(sbase + row * 128 + ((cg ^ (row & 7)) << 4),
                (const char*)A + (size_t)row * (DD*2) + cg * 16);
    }
#pragma unroll
    for (int p = 0; p < 2; p++) {           // B1: 512 x 16B
        int idx = p * NTHREADS + tid;
        int row = idx >> 3, cg = idx & 7;
        cp16(sbase + A_TILE_B + row * 128 + ((cg ^ (row & 7)) << 4),
             (const char*)B1 + (size_t)row * (DD*2) + cg * 16);
    }
#pragma unroll
    for (int p = 0; p < 2; p++) {           // B2: 512 x 16B
        int idx = p * NTHREADS + tid;
        int row = idx >> 3, cg = idx & 7;
        cp16(sbase + A_TILE_B + B_TILE_B + row * 128 + ((cg ^ (row & 7)) << 4),
             (const char*)B2 + (size_t)row * (DD*2) + cg * 16);
    }
}

// 3-stage double-output fp16 GEMM mainloop, 8 warps, ldmatrix fragment loads.
// R14 SCHEDULE (frozen — best measured). ONE barrier per chunk:
//  - entry to chunk c: prior wait->barrier pair certified stage c for ALL warps.
//  - mid-chunk load(c+2) targets stage (c-1)%3, dead since the last barrier.
//  - end of chunk: cp_wait THEN barrier (publishes every warp's completions).
// Warp tile: 32M (wm = wid&3) x 32N (wn = wid>>2) per matrix.
__device__ __forceinline__ void run_gemm2(uint32_t sb,
                                          const __half* A, const __half* B1, const __half* B2,
                                          int tid, float acc1[2][4][4], float acc2[2][4][4])
{
    const int wid = tid >> 5, lane = tid & 31;
    const int wm = wid & 3, wn = wid >> 2;
    const int l7 = lane & 7;

    const int rowA = wm * 32 + (lane & 15);
    const int hA   = lane >> 4;
    const int rowB = wn * 32 + l7 + ((lane >> 4) << 3);
    const int hB   = (lane >> 3) & 1;

#pragma unroll
    for (int m = 0; m < 2; m++)
#pragma unroll
        for (int nt = 0; nt < 4; nt++)
#pragma unroll
            for (int r = 0; r < 4; r++) { acc1[m][nt][r] = 0.f; acc2[m][nt][r] = 0.f; }

    // Prologue: stage 0,1 in flight; certify stage 0 for all warps.
    load_stage(sb + 0*STAGE_B, A,      B1,      B2,      tid); cp_commit();
    load_stage(sb + 1*STAGE_B, A + BK, B1 + BK, B2 + BK, tid); cp_commit();
    cp_wait<1>();
    __syncthreads();

    for (int c = 0; c < NCHUNK; c++) {
        const int s = c % NSTAGE;
        const uint32_t sA  = sb + s * STAGE_B;
        const uint32_t sB1 = sA + A_TILE_B;
        const uint32_t sB2 = sB1 + B_TILE_B;
        const uint32_t baseA0 = sA  + (uint32_t)rowA * 128;          // m=0
        const uint32_t baseA1 = baseA0 + 16 * 128;                   // m=1
        const uint32_t bB10 = sB1 + (uint32_t)rowB * 128;            // pair 0
        const uint32_t bB11 = bB10 + 16 * 128;                       // pair 1
        const uint32_t bB20 = sB2 + (uint32_t)rowB * 128;
        const uint32_t bB21 = bB20 + 16 * 128;

#pragma unroll
        for (int half_c = 0; half_c < 2; half_c++) {
            // Mid-chunk: issue next-next chunk's loads between the two MMA halves.
            if (half_c == 1 && c + 2 < NCHUNK) {
                const int k0 = (c + 2) * BK;
                load_stage(sb + ((c + 2) % NSTAGE) * STAGE_B, A + k0, B1 + k0, B2 + k0, tid);
                cp_commit();
            }
#pragma unroll
            for (int kss = 0; kss < 2; kss++) {
                const int ks = half_c * 2 + kss;
                const uint32_t gA = (uint32_t)((((ks << 1) | hA) ^ l7) << 4);
                const uint32_t gB = (uint32_t)((((ks << 1) | hB) ^ l7) << 4);

                uint32_t af0[4], af1[4];
                LDSM4(af0[0], af0[1], af0[2], af0[3], baseA0 + gA);
                LDSM4(af1[0], af1[1], af1[2], af1[3], baseA1 + gA);

                uint32_t bf1r[4][2], bf2r[4][2];
                LDSM4(bf1r[0][0], bf1r[0][1], bf1r[1][0], bf1r[1][1], bB10 + gB);
                LDSM4(bf1r[2][0], bf1r[2][1], bf1r[3][0], bf1r[3][1], bB11 + gB);
                LDSM4(bf2r[0][0], bf2r[0][1], bf2r[1][0], bf2r[1][1], bB20 + gB);
                LDSM4(bf2r[2][0], bf2r[2][1], bf2r[3][0], bf2r[3][1], bB21 + gB);

#pragma unroll
                for (int nt = 0; nt < 4; nt++) {
                    mma_f16(acc1[0][nt], af0, bf1r[nt]);
                    mma_f16(acc2[0][nt], af0, bf2r[nt]);
                    mma_f16(acc1[1][nt], af1, bf1r[nt]);
                    mma_f16(acc2[1][nt], af1, bf2r[nt]);
                }
            }
        }

        // Certify chunk c+1 for the next iteration, then the single barrier.
        if (c + 2 < NCHUNK)      cp_wait<1>();   // outstanding {c+1, c+2} -> oldest done
        else if (c + 1 < NCHUNK) cp_wait<0>();   // only {c+1} outstanding -> drain
        __syncthreads();
    }
}

// ---------------------------------------------------------------------------
// Kernel 0: convert all 5 tensors fp32 -> fp16 in ONE launch (flat index)
// ---------------------------------------------------------------------------
__global__ void cvt_all_kernel(const float4* __restrict__ x,
                               const float4* __restrict__ wq, const float4* __restrict__ wk,
                               const float4* __restrict__ wv, const float4* __restrict__ wg,
                               uint2* __restrict__ xo,
                               uint2* __restrict__ qo, uint2* __restrict__ ko,
                               uint2* __restrict__ vo, uint2* __restrict__ go,
                               int nX4, int nW4)
{
    int i = blockIdx.x * blockDim.x + threadIdx.x;
    const float4* s; uint2* d; int j;
    if (i < nX4) { s = x; d = xo; j = i; }
    else {
        int r = i - nX4;
        int t = r / nW4;          // 0..3
        j = r - t * nW4;
        if (j >= nW4) return;
        switch (t) {
            case 0: s = wq; d = qo; break;
            case 1: s = wk; d = ko; break;
            case 2: s = wv; d = vo; break;
            case 3: s = wg; d = go; break;
            default: return;
        }
    }
    float4 v = s[j];
    __half2 h0 = __floats2half2_rn(v.x, v.y);
    __half2 h1 = __floats2half2_rn(v.z, v.w);
    uint2 o;
    o.x = *(uint32_t*)&h0;
    o.y = *(uint32_t*)&h1;
    d[j] = o;
}

// ---------------------------------------------------------------------------
// Kernel 1: K=phi(X@Wk^T), V=X@Wv^T; per-rowblock column sums of phi(K), phi(K)*V.
// In-register epilogue: shuffle-reduce over rows, tiny smem fold across warps.
// grid = (DD/BN=16, NRB=128), 256 threads
// ---------------------------------------------------------------------------
__global__ void __launch_bounds__(NTHREADS, 2)
stats_kernel(const __half* __restrict__ X, const __half* __restrict__ Wk,
             const __half* __restrict__ Wv)
{
    extern __shared__ char smem[];
    uint32_t sb = smem_u32(smem);
    const int tid = threadIdx.x;
    const int row0 = blockIdx.y * BM, col0 = blockIdx.x * BN;

    float accK[2][4][4], accV[2][4][4];
    run_gemm2(sb, X + (size_t)row0 * DD, Wk + (size_t)col0 * DD,
              Wv + (size_t)col0 * DD, tid, accK, accV);

    const int wid = tid >> 5, lane = tid & 31;
    const int wm = wid & 3, wn = wid >> 2;
    const int lm4 = lane & 3;

    // Thread-local: sum over this thread's 4 rows for each of its 8 columns.
    float pk[4][2], pkv[4][2];
#pragma unroll
    for (int nt = 0; nt < 4; nt++)
#pragma unroll
        for (int cc = 0; cc < 2; cc++) {
            float sk = 0.f, skv = 0.f;
#pragma unroll
            for (int m = 0; m < 2; m++)
#pragma unroll
                for (int half = 0; half < 2; half++) {
                    float kv = phi_f(accK[m][nt][half * 2 + cc]);
                    sk  += kv;
                    skv += kv * accV[m][nt][half * 2 + cc];
                }
            pk[nt][cc] = sk;
            pkv[nt][cc] = skv;
        }

    // Reduce over the l4 axis (lanes lane&3 == const, 8 rows apart): 3 shuffles.
#pragma unroll
    for (int nt = 0; nt < 4; nt++)
#pragma unroll
        for (int cc = 0; cc < 2; cc++) {
#pragma unroll
            for (int off = 16; off >= 4; off >>= 1) {
                pk[nt][cc]  += __shfl_down_sync(0xffffffffu, pk[nt][cc],  off);
                pkv[nt][cc] += __shfl_down_sync(0xffffffffu, pkv[nt][cc], off);
            }
        }

    // Lanes 0-3 hold the 32-row sums for their columns; fold across wm warps.
    float* partA = (float*)(smem + OFF_STATS);        // [4 wm][64]
    float* partB = partA + 256;                       // [4 wm][64]
    if (lane < 4) {
#pragma unroll
        for (int nt = 0; nt < 4; nt++) {
            const int col = wn * 32 + nt * 8 + lm4 * 2;
            partA[wm * 64 + col]     = pk[nt][0];
            partA[wm * 64 + col + 1] = pk[nt][1];
            partB[wm * 64 + col]     = pkv[nt][0];
            partB[wm * 64 + col + 1] = pkv[nt][1];
        }
    }
    __syncthreads();
    if (tid < 64) {
        float sa = partA[tid] + partA[64 + tid] + partA[128 + tid] + partA[192 + tid];
        float sv = partB[tid] + partB[64 + tid] + partB[128 + tid] + partB[192 + tid];
        size_t o = (size_t)blockIdx.y * DD + col0 + tid;
        g_pk[o]  = sa;
        g_pkv[o] = sv;
    }
}

// ---------------------------------------------------------------------------
// Kernel 2: fold 32 row-block partials per batch (vectorized float4 over d)
// ---------------------------------------------------------------------------
__global__ void reduce_stats_kernel() {
    int i4 = blockIdx.x * blockDim.x + threadIdx.x;   // over BB*DD/4 = 4096
    if (i4 >= BB * DD / 4) return;
    int b = i4 >> 8;                // DD/4 = 256 float4 per batch
    int d4 = i4 & 255;
    float4 sk = make_float4(0.f, 0.f, 0.f, 0.f);
    float4 skv = make_float4(0.f, 0.f, 0.f, 0.f);
    int rb0 = b * (NRB / BB);
    for (int rb = 0; rb < NRB / BB; rb++) {
        const float4 pk  = *(const float4*)&g_pk [(size_t)(rb0 + rb) * DD + d4 * 4];
        const float4 pkv = *(const float4*)&g_pkv[(size_t)(rb0 + rb) * DD + d4 * 4];
        sk.x += pk.x;  sk.y += pk.y;  sk.z += pk.z;  sk.w += pk.w;
        skv.x += pkv.x; skv.y += pkv.y; skv.z += pkv.z; skv.w += pkv.w;
    }
    *(float4*)&g_ksum [b * DD + d4 * 4] = sk;
    *(float4*)&g_kvsum[b * DD + d4 * 4] = skv;
}

// ---------------------------------------------------------------------------
// Kernel 3: Q=phi(X@Wq^T), G=X@Wg^T; s,z per row; gated output.
// grid = (16, 128); block column == one head (BN = HD = 64). 256 threads.
// ---------------------------------------------------------------------------
__global__ void __launch_bounds__(NTHREADS, 2)
out_kernel(const __half* __restrict__ Xh, const __half* __restrict__ Wq,
           const __half* __restrict__ Wg, const float* __restrict__ bgv,
           const float* __restrict__ X, float* __restrict__ out)
{
    extern __shared__ char smem[];
    uint32_t sb = smem_u32(smem);
    const int tid = threadIdx.x;
    const int row0 = blockIdx.y * BM, col0 = blockIdx.x * BN;
    const int b = row0 / TT;

    // Dedicated (non-aliased) stats region
    float* kvsS  = (float*)(smem + OFF_STATS);   // [64]
    float* ksS   = kvsS + 64;                    // [64]
    float* bgS   = ksS + 64;                     // [64]
    float* ratio = bgS + 64;                     // [128]
    if (tid < 64) {
        kvsS[tid] = g_kvsum[b * DD + col0 + tid];
        ksS[tid]  = g_ksum [b * DD + col0 + tid];
        bgS[tid]  = bgv[col0 + tid];
    }
    __syncthreads();

    float accQ[2][4][4], accG[2][4][4];
    run_gemm2(sb, Xh + (size_t)row0 * DD, Wq + (size_t)col0 * DD,
              Wg + (size_t)col0 * DD, tid, accQ, accG);

    const int wid = tid >> 5, lane = tid & 31;
    const int wm = wid & 3, wn = wid >> 2;
    const int l4 = lane >> 2, lm4 = lane & 3;

    // Partial s,z per (row, thread-slice): 8 partials per row
    float* red_s = (float*)smem;          // [128][8]
    float* red_z = red_s + 128 * 8;       // [128][8]
    const int sl = wn * 4 + lm4;
#pragma unroll
    for (int m = 0; m < 2; m++)
#pragma unroll
        for (int half = 0; half < 2; half++) {
            const int row = wm * 32 + m * 16 + l4 + half * 8;
            float s = 0.f, z = 0.f;
#pragma unroll
            for (int nt = 0; nt < 4; nt++) {
                const int col = wn * 32 + nt * 8 + lm4 * 2;
#pragma unroll
                for (int cc = 0; cc < 2; cc++) {
                    float q = phi_f(accQ[m][nt][half * 2 + cc]);
                    s += q * kvsS[col + cc];
                    z += q * ksS[col + cc];
                }
            }
            red_s[row * 8 + sl] = s;
            red_z[row * 8 + sl] = z;
        }
    __syncthreads();
    if (tid < 128) {
        float s = 0.f, z = 0.f;
#pragma unroll
        for (int j = 0; j < 8; j++) { s += red_s[tid * 8 + j]; z += red_z[tid * 8 + j]; }
        ratio[tid] = s / (z + EPSF);
    }
    __syncthreads();

    // Gate + mix, direct float2 stores (uses ORIGINAL fp32 X for the mix)
#pragma unroll
    for (int m = 0; m < 2; m++)
#pragma unroll
        for (int half = 0; half < 2; half++) {
            const int row = wm * 32 + m * 16 + l4 + half * 8;
            const float rt = ratio[row];
            const size_t rbase = (size_t)(row0 + row) * DD + col0;
#pragma unroll
            for (int nt = 0; nt < 4; nt++) {
                const int col = wn * 32 + nt * 8 + lm4 * 2;
                const float2 x2 = *(const float2*)&X[rbase + col];
                float g0 = sigm(accG[m][nt][half * 2 + 0] + bgS[col + 0]);
                float g1 = sigm(accG[m][nt][half * 2 + 1] + bgS[col + 1]);
                float2 o;
                o.x = g0 * rt + (1.f - g0) * x2.x;
                o.y = g1 * rt + (1.f - g1) * x2.y;
                *(float2*)&out[rbase + col] = o;
            }
        }
}

// ---------------------------------------------------------------------------
extern "C" void kernel_launch(void* const* d_in, const int* in_sizes, int n_in,
                              void* d_out, int out_size)
{
    const float* x  = (const float*)d_in[0];
    const float* Wq = (const float*)d_in[1];
    const float* Wk = (const float*)d_in[2];
    const float* Wv = (const float*)d_in[3];
    // d_in[4] = Wo — unused by the reference computation
    const float* Wg = (const float*)d_in[5];
    const float* bg = (const float*)d_in[6];
    float* out = (float*)d_out;

    cudaFuncSetAttribute(stats_kernel, cudaFuncAttributeMaxDynamicSharedMemorySize, SMEM_TOTAL);
    cudaFuncSetAttribute(out_kernel,   cudaFuncAttributeMaxDynamicSharedMemorySize, SMEM_TOTAL);

    __half *Xh, *Wqh, *Wkh, *Wvh, *Wgh;
    cudaGetSymbolAddress((void**)&Xh,  g_Xh);
    cudaGetSymbolAddress((void**)&Wqh, g_Wqh);
    cudaGetSymbolAddress((void**)&Wkh, g_Wkh);
    cudaGetSymbolAddress((void**)&Wvh, g_Wvh);
    cudaGetSymbolAddress((void**)&Wgh, g_Wgh);

    const int nX4 = BB*TT*DD/4, nW4 = DD*DD/4;
    const int nTot = nX4 + 4 * nW4;
    cvt_all_kernel<<<(nTot + 255)/256, 256>>>(
        (const float4*)x, (const float4*)Wq, (const float4*)Wk,
        (const float4*)Wv, (const float4*)Wg,
        (uint2*)Xh, (uint2*)Wqh, (uint2*)Wkh, (uint2*)Wvh, (uint2*)Wgh, nX4, nW4);

    dim3 grid(DD / BN, NRB);   // (16, 128)
    stats_kernel<<<grid, NTHREADS, SMEM_TOTAL>>>(Xh, Wkh, Wvh);
    reduce_stats_kernel<<<8, 256>>>();
    out_kernel<<<grid, NTHREADS, SMEM_TOTAL>>>(Xh, Wqh, Wgh, bg, x, out);
}

// round 17
// speedup vs baseline: 1.5232x; 1.0798x over previous
#include <cuda_runtime.h>
#include <cuda_fp16.h>
#include <cstdint>
#include <math.h>

#define DD 1024
#define TT 4096
#define BB 4
#define EPSF 1e-6f

#define BM 128
#define BN 64            // per weight matrix; one head per block in out_kernel
#define BK 64            // halves per K-chunk (=128 bytes/row)
#define NCHUNK (DD/BK)   // 16
#define NTHREADS 256
#define NSTAGE 3

#define A_TILE_B  (BM*BK*2)                 // 16384
#define B_TILE_B  (BN*BK*2)                 // 8192
#define STAGE_B   (A_TILE_B + 2*B_TILE_B)   // 32768
#define OFF_STATS (NSTAGE*STAGE_B)          // 98304
#define SMEM_TOTAL (OFF_STATS + 2048)       // 100352

#define NRB (BB*TT/BM)   // 128 row blocks

// Deterministic two-stage reduction buffers
__device__ float g_pk  [NRB*DD];
__device__ float g_pkv [NRB*DD];
__device__ float g_ksum [BB*DD];
__device__ float g_kvsum[BB*DD];
// fp16 copies (converted once per launch)
__device__ __align__(16) __half g_Xh [BB*TT*DD];
__device__ __align__(16) __half g_Wqh[DD*DD];
__device__ __align__(16) __half g_Wkh[DD*DD];
__device__ __align__(16) __half g_Wvh[DD*DD];
__device__ __align__(16) __half g_Wgh[DD*DD];

// ---------------------------------------------------------------- helpers ---
__device__ __forceinline__ uint32_t smem_u32(const void* p) {
    uint32_t a;
    asm("{ .reg .u64 t; cvta.to.shared.u64 t, %1; cvt.u32.u64 %0, t; }" : "=r"(a) : "l"(p));
    return a;
}
__device__ __forceinline__ void cp16(uint32_t dst, const void* src) {
    asm volatile("cp.async.cg.shared.global [%0], [%1], 16;" :: "r"(dst), "l"(src));
}
__device__ __forceinline__ void cp_commit() { asm volatile("cp.async.commit_group;" ::: "memory"); }
template <int N> __device__ __forceinline__ void cp_wait() {
    asm volatile("cp.async.wait_group %0;" :: "n"(N) : "memory");
}
__device__ __forceinline__ void mma_f16(float* d, const uint32_t* a, const uint32_t* b) {
    asm volatile("mma.sync.aligned.m16n8k16.row.col.f32.f16.f16.f32 "
                 "{%0,%1,%2,%3}, {%4,%5,%6,%7}, {%8,%9}, {%0,%1,%2,%3};"
                 : "+f"(d[0]), "+f"(d[1]), "+f"(d[2]), "+f"(d[3])
                 : "r"(a[0]), "r"(a[1]), "r"(a[2]), "r"(a[3]), "r"(b[0]), "r"(b[1]));
}
#define LDSM4(r0, r1, r2, r3, addr) \
    asm volatile("ldmatrix.sync.aligned.m8n8.x4.shared.b16 {%0,%1,%2,%3}, [%4];" \
                 : "=r"(r0), "=r"(r1), "=r"(r2), "=r"(r3) : "r"(addr))
__device__ __forceinline__ float phi_f(float x) { return x > 0.f ? x + 1.f : __expf(x); }
__device__ __forceinline__ float sigm(float x) { return 1.f / (1.f + __expf(-x)); }

// Load one K-chunk into a stage: A 128x64h, B1 64x64h, B2 64x64h (256 threads)
// Rows are 128 bytes; 16B groups XORed with (row&7) — conflict-free.
__device__ __forceinline__ void load_stage(uint32_t sbase,
                                           const __half* A, const __half* B1, const __half* B2,
                                           int tid)
{
#pragma unroll
    for (int p = 0; p < 4; p++) {           // A: 1024 x 16B
        int idx = p * NTHREADS + tid;
        int row = idx >> 3, cg = idx & 7;
        cp16(sbase + row * 128 + ((cg ^ (row & 7)) << 4),
             (const char*)A + (size_t)row * (DD*2) + cg * 16);
    }
#pragma unroll
    for (int p = 0; p < 2; p++) {           // B1: 512 x 16B
        int idx = p * NTHREADS + tid;
        int row = idx >> 3, cg = idx & 7;
        cp16(sbase + A_TILE_B + row * 128 + ((cg ^ (row & 7)) << 4),
             (const char*)B1 + (size_t)row * (DD*2) + cg * 16);
    }
#pragma unroll
    for (int p = 0; p < 2; p++) {           // B2: 512 x 16B
        int idx = p * NTHREADS + tid;
        int row = idx >> 3, cg = idx & 7;
        cp16(sbase + A_TILE_B + B_TILE_B + row * 128 + ((cg ^ (row & 7)) << 4),
             (const char*)B2 + (size_t)row * (DD*2) + cg * 16);
    }
}

// 3-stage double-output fp16 GEMM mainloop, 8 warps, ldmatrix fragment loads.
// R14 SCHEDULE (frozen — best measured). ONE barrier per chunk:
//  - entry to chunk c: prior wait->barrier pair certified stage c for ALL warps.
//  - mid-chunk load(c+2) targets stage (c-1)%3, dead since the last barrier.
//  - end of chunk: cp_wait THEN barrier (publishes every warp's completions).
// Warp tile: 32M (wm = wid&3) x 32N (wn = wid>>2) per matrix.
__device__ __forceinline__ void run_gemm2(uint32_t sb,
                                          const __half* A, const __half* B1, const __half* B2,
                                          int tid, float acc1[2][4][4], float acc2[2][4][4])
{
    const int wid = tid >> 5, lane = tid & 31;
    const int wm = wid & 3, wn = wid >> 2;
    const int l7 = lane & 7;

    const int rowA = wm * 32 + (lane & 15);
    const int hA   = lane >> 4;
    const int rowB = wn * 32 + l7 + ((lane >> 4) << 3);
    const int hB   = (lane >> 3) & 1;

#pragma unroll
    for (int m = 0; m < 2; m++)
#pragma unroll
        for (int nt = 0; nt < 4; nt++)
#pragma unroll
            for (int r = 0; r < 4; r++) { acc1[m][nt][r] = 0.f; acc2[m][nt][r] = 0.f; }

    // Prologue: stage 0,1 in flight; certify stage 0 for all warps.
    load_stage(sb + 0*STAGE_B, A,      B1,      B2,      tid); cp_commit();
    load_stage(sb + 1*STAGE_B, A + BK, B1 + BK, B2 + BK, tid); cp_commit();
    cp_wait<1>();
    __syncthreads();

    for (int c = 0; c < NCHUNK; c++) {
        const int s = c % NSTAGE;
        const uint32_t sA  = sb + s * STAGE_B;
        const uint32_t sB1 = sA + A_TILE_B;
        const uint32_t sB2 = sB1 + B_TILE_B;
        const uint32_t baseA0 = sA  + (uint32_t)rowA * 128;          // m=0
        const uint32_t baseA1 = baseA0 + 16 * 128;                   // m=1
        const uint32_t bB10 = sB1 + (uint32_t)rowB * 128;            // pair 0
        const uint32_t bB11 = bB10 + 16 * 128;                       // pair 1
        const uint32_t bB20 = sB2 + (uint32_t)rowB * 128;
        const uint32_t bB21 = bB20 + 16 * 128;

#pragma unroll
        for (int half_c = 0; half_c < 2; half_c++) {
            // Mid-chunk: issue next-next chunk's loads between the two MMA halves.
            if (half_c == 1 && c + 2 < NCHUNK) {
                const int k0 = (c + 2) * BK;
                load_stage(sb + ((c + 2) % NSTAGE) * STAGE_B, A + k0, B1 + k0, B2 + k0, tid);
                cp_commit();
            }
#pragma unroll
            for (int kss = 0; kss < 2; kss++) {
                const int ks = half_c * 2 + kss;
                const uint32_t gA = (uint32_t)((((ks << 1) | hA) ^ l7) << 4);
                const uint32_t gB = (uint32_t)((((ks << 1) | hB) ^ l7) << 4);

                uint32_t af0[4], af1[4];
                LDSM4(af0[0], af0[1], af0[2], af0[3], baseA0 + gA);
                LDSM4(af1[0], af1[1], af1[2], af1[3], baseA1 + gA);

                uint32_t bf1r[4][2], bf2r[4][2];
                LDSM4(bf1r[0][0], bf1r[0][1], bf1r[1][0], bf1r[1][1], bB10 + gB);
                LDSM4(bf1r[2][0], bf1r[2][1], bf1r[3][0], bf1r[3][1], bB11 + gB);
                LDSM4(bf2r[0][0], bf2r[0][1], bf2r[1][0], bf2r[1][1], bB20 + gB);
                LDSM4(bf2r[2][0], bf2r[2][1], bf2r[3][0], bf2r[3][1], bB21 + gB);

#pragma unroll
                for (int nt = 0; nt < 4; nt++) {
                    mma_f16(acc1[0][nt], af0, bf1r[nt]);
                    mma_f16(acc2[0][nt], af0, bf2r[nt]);
                    mma_f16(acc1[1][nt], af1, bf1r[nt]);
                    mma_f16(acc2[1][nt], af1, bf2r[nt]);
                }
            }
        }

        // Certify chunk c+1 for the next iteration, then the single barrier.
        if (c + 2 < NCHUNK)      cp_wait<1>();   // outstanding {c+1, c+2} -> oldest done
        else if (c + 1 < NCHUNK) cp_wait<0>();   // only {c+1} outstanding -> drain
        __syncthreads();
    }
}

// ---------------------------------------------------------------------------
// Kernel 0: convert all 5 tensors fp32 -> fp16 in ONE launch (flat index)
// ---------------------------------------------------------------------------
__global__ void cvt_all_kernel(const float4* __restrict__ x,
                               const float4* __restrict__ wq, const float4* __restrict__ wk,
                               const float4* __restrict__ wv, const float4* __restrict__ wg,
                               uint2* __restrict__ xo,
                               uint2* __restrict__ qo, uint2* __restrict__ ko,
                               uint2* __restrict__ vo, uint2* __restrict__ go,
                               int nX4, int nW4)
{
    int i = blockIdx.x * blockDim.x + threadIdx.x;
    const float4* s; uint2* d; int j;
    if (i < nX4) { s = x; d = xo; j = i; }
    else {
        int r = i - nX4;
        int t = r / nW4;          // 0..3
        j = r - t * nW4;
        if (j >= nW4) return;
        switch (t) {
            case 0: s = wq; d = qo; break;
            case 1: s = wk; d = ko; break;
            case 2: s = wv; d = vo; break;
            case 3: s = wg; d = go; break;
            default: return;
        }
    }
    float4 v = s[j];
    __half2 h0 = __floats2half2_rn(v.x, v.y);
    __half2 h1 = __floats2half2_rn(v.z, v.w);
    uint2 o;
    o.x = *(uint32_t*)&h0;
    o.y = *(uint32_t*)&h1;
    d[j] = o;
}

// ---------------------------------------------------------------------------
// Kernel 1: K=phi(X@Wk^T), V=X@Wv^T; per-rowblock column sums of phi(K), phi(K)*V.
// In-register epilogue: shuffle-reduce over rows, tiny smem fold across warps.
// grid = (DD/BN=16, NRB=128), 256 threads
// ---------------------------------------------------------------------------
__global__ void __launch_bounds__(NTHREADS, 2)
stats_kernel(const __half* __restrict__ X, const __half* __restrict__ Wk,
             const __half* __restrict__ Wv)
{
    extern __shared__ char smem[];
    uint32_t sb = smem_u32(smem);
    const int tid = threadIdx.x;
    const int row0 = blockIdx.y * BM, col0 = blockIdx.x * BN;

    float accK[2][4][4], accV[2][4][4];
    run_gemm2(sb, X + (size_t)row0 * DD, Wk + (size_t)col0 * DD,
              Wv + (size_t)col0 * DD, tid, accK, accV);

    const int wid = tid >> 5, lane = tid & 31;
    const int wm = wid & 3, wn = wid >> 2;
    const int lm4 = lane & 3;

    // Thread-local: sum over this thread's 4 rows for each of its 8 columns.
    float pk[4][2], pkv[4][2];
#pragma unroll
    for (int nt = 0; nt < 4; nt++)
#pragma unroll
        for (int cc = 0; cc < 2; cc++) {
            float sk = 0.f, skv = 0.f;
#pragma unroll
            for (int m = 0; m < 2; m++)
#pragma unroll
                for (int half = 0; half < 2; half++) {
                    float kv = phi_f(accK[m][nt][half * 2 + cc]);
                    sk  += kv;
                    skv += kv * accV[m][nt][half * 2 + cc];
                }
            pk[nt][cc] = sk;
            pkv[nt][cc] = skv;
        }

    // Reduce over the l4 axis (lanes lane&3 == const, 8 rows apart): 3 shuffles.
#pragma unroll
    for (int nt = 0; nt < 4; nt++)
#pragma unroll
        for (int cc = 0; cc < 2; cc++) {
#pragma unroll
            for (int off = 16; off >= 4; off >>= 1) {
                pk[nt][cc]  += __shfl_down_sync(0xffffffffu, pk[nt][cc],  off);
                pkv[nt][cc] += __shfl_down_sync(0xffffffffu, pkv[nt][cc], off);
            }
        }

    // Lanes 0-3 hold the 32-row sums for their columns; fold across wm warps.
    float* partA = (float*)(smem + OFF_STATS);        // [4 wm][64]
    float* partB = partA + 256;                       // [4 wm][64]
    if (lane < 4) {
#pragma unroll
        for (int nt = 0; nt < 4; nt++) {
            const int col = wn * 32 + nt * 8 + lm4 * 2;
            partA[wm * 64 + col]     = pk[nt][0];
            partA[wm * 64 + col + 1] = pk[nt][1];
            partB[wm * 64 + col]     = pkv[nt][0];
            partB[wm * 64 + col + 1] = pkv[nt][1];
        }
    }
    __syncthreads();
    if (tid < 64) {
        float sa = partA[tid] + partA[64 + tid] + partA[128 + tid] + partA[192 + tid];
        float sv = partB[tid] + partB[64 + tid] + partB[128 + tid] + partB[192 + tid];
        size_t o = (size_t)blockIdx.y * DD + col0 + tid;
        g_pk[o]  = sa;
        g_pkv[o] = sv;
    }
}

// ---------------------------------------------------------------------------
// Kernel 2: fold 32 row-block partials per batch (vectorized float4 over d)
// ---------------------------------------------------------------------------
__global__ void reduce_stats_kernel() {
    int i4 = blockIdx.x * blockDim.x + threadIdx.x;   // over BB*DD/4 = 4096
    if (i4 >= BB * DD / 4) return;
    int b = i4 >> 8;                // DD/4 = 256 float4 per batch
    int d4 = i4 & 255;
    float4 sk = make_float4(0.f, 0.f, 0.f, 0.f);
    float4 skv = make_float4(0.f, 0.f, 0.f, 0.f);
    int rb0 = b * (NRB / BB);
    for (int rb = 0; rb < NRB / BB; rb++) {
        const float4 pk  = *(const float4*)&g_pk [(size_t)(rb0 + rb) * DD + d4 * 4];
        const float4 pkv = *(const float4*)&g_pkv[(size_t)(rb0 + rb) * DD + d4 * 4];
        sk.x += pk.x;  sk.y += pk.y;  sk.z += pk.z;  sk.w += pk.w;
        skv.x += pkv.x; skv.y += pkv.y; skv.z += pkv.z; skv.w += pkv.w;
    }
    *(float4*)&g_ksum [b * DD + d4 * 4] = sk;
    *(float4*)&g_kvsum[b * DD + d4 * 4] = skv;
}

// ---------------------------------------------------------------------------
// Kernel 3: Q=phi(X@Wq^T), G=X@Wg^T; s,z per row; gated output.
// grid = (16, 128); block column == one head (BN = HD = 64). 256 threads.
// ---------------------------------------------------------------------------
__global__ void __launch_bounds__(NTHREADS, 2)
out_kernel(const __half* __restrict__ Xh, const __half* __restrict__ Wq,
           const __half* __restrict__ Wg, const float* __restrict__ bgv,
           const float* __restrict__ X, float* __restrict__ out)
{
    extern __shared__ char smem[];
    uint32_t sb = smem_u32(smem);
    const int tid = threadIdx.x;
    const int row0 = blockIdx.y * BM, col0 = blockIdx.x * BN;
    const int b = row0 / TT;

    // Dedicated (non-aliased) stats region
    float* kvsS  = (float*)(smem + OFF_STATS);   // [64]
    float* ksS   = kvsS + 64;                    // [64]
    float* bgS   = ksS + 64;                     // [64]
    float* ratio = bgS + 64;                     // [128]
    if (tid < 64) {
        kvsS[tid] = g_kvsum[b * DD + col0 + tid];
        ksS[tid]  = g_ksum [b * DD + col0 + tid];
        bgS[tid]  = bgv[col0 + tid];
    }
    __syncthreads();

    float accQ[2][4][4], accG[2][4][4];
    run_gemm2(sb, Xh + (size_t)row0 * DD, Wq + (size_t)col0 * DD,
              Wg + (size_t)col0 * DD, tid, accQ, accG);

    const int wid = tid >> 5, lane = tid & 31;
    const int wm = wid & 3, wn = wid >> 2;
    const int l4 = lane >> 2, lm4 = lane & 3;

    // Partial s,z per (row, thread-slice): 8 partials per row
    float* red_s = (float*)smem;          // [128][8]
    float* red_z = red_s + 128 * 8;       // [128][8]
    const int sl = wn * 4 + lm4;
#pragma unroll
    for (int m = 0; m < 2; m++)
#pragma unroll
        for (int half = 0; half < 2; half++) {
            const int row = wm * 32 + m * 16 + l4 + half * 8;
            float s = 0.f, z = 0.f;
#pragma unroll
            for (int nt = 0; nt < 4; nt++) {
                const int col = wn * 32 + nt * 8 + lm4 * 2;
#pragma unroll
                for (int cc = 0; cc < 2; cc++) {
                    float q = phi_f(accQ[m][nt][half * 2 + cc]);
                    s += q * kvsS[col + cc];
                    z += q * ksS[col + cc];
                }
            }
            red_s[row * 8 + sl] = s;
            red_z[row * 8 + sl] = z;
        }
    __syncthreads();
    if (tid < 128) {
        float s = 0.f, z = 0.f;
#pragma unroll
        for (int j = 0; j < 8; j++) { s += red_s[tid * 8 + j]; z += red_z[tid * 8 + j]; }
        ratio[tid] = s / (z + EPSF);
    }
    __syncthreads();

    // Gate + mix, direct float2 stores (uses ORIGINAL fp32 X for the mix)
#pragma unroll
    for (int m = 0; m < 2; m++)
#pragma unroll
        for (int half = 0; half < 2; half++) {
            const int row = wm * 32 + m * 16 + l4 + half * 8;
            const float rt = ratio[row];
            const size_t rbase = (size_t)(row0 + row) * DD + col0;
#pragma unroll
            for (int nt = 0; nt < 4; nt++) {
                const int col = wn * 32 + nt * 8 + lm4 * 2;
                const float2 x2 = *(const float2*)&X[rbase + col];
                float g0 = sigm(accG[m][nt][half * 2 + 0] + bgS[col + 0]);
                float g1 = sigm(accG[m][nt][half * 2 + 1] + bgS[col + 1]);
                float2 o;
                o.x = g0 * rt + (1.f - g0) * x2.x;
                o.y = g1 * rt + (1.f - g1) * x2.y;
                *(float2*)&out[rbase + col] = o;
            }
        }
}

// ---------------------------------------------------------------------------
extern "C" void kernel_launch(void* const* d_in, const int* in_sizes, int n_in,
                              void* d_out, int out_size)
{
    const float* x  = (const float*)d_in[0];
    const float* Wq = (const float*)d_in[1];
    const float* Wk = (const float*)d_in[2];
    const float* Wv = (const float*)d_in[3];
    // d_in[4] = Wo — unused by the reference computation
    const float* Wg = (const float*)d_in[5];
    const float* bg = (const float*)d_in[6];
    float* out = (float*)d_out;

    cudaFuncSetAttribute(stats_kernel, cudaFuncAttributeMaxDynamicSharedMemorySize, SMEM_TOTAL);
    cudaFuncSetAttribute(out_kernel,   cudaFuncAttributeMaxDynamicSharedMemorySize, SMEM_TOTAL);

    __half *Xh, *Wqh, *Wkh, *Wvh, *Wgh;
    cudaGetSymbolAddress((void**)&Xh,  g_Xh);
    cudaGetSymbolAddress((void**)&Wqh, g_Wqh);
    cudaGetSymbolAddress((void**)&Wkh, g_Wkh);
    cudaGetSymbolAddress((void**)&Wvh, g_Wvh);
    cudaGetSymbolAddress((void**)&Wgh, g_Wgh);

    const int nX4 = BB*TT*DD/4, nW4 = DD*DD/4;
    const int nTot = nX4 + 4 * nW4;
    cvt_all_kernel<<<(nTot + 255)/256, 256>>>(
        (const float4*)x, (const float4*)Wq, (const float4*)Wk,
        (const float4*)Wv, (const float4*)Wg,
        (uint2*)Xh, (uint2*)Wqh, (uint2*)Wkh, (uint2*)Wvh, (uint2*)Wgh, nX4, nW4);

    dim3 grid(DD / BN, NRB);   // (16, 128)
    stats_kernel<<<grid, NTHREADS, SMEM_TOTAL>>>(Xh, Wkh, Wvh);
    reduce_stats_kernel<<<8, 256>>>();
    out_kernel<<<grid, NTHREADS, SMEM_TOTAL>>>(Xh, Wqh, Wgh, bg, x, out);
}